// round 5
// baseline (speedup 1.0000x reference)
#include <cuda_runtime.h>

// ---------------------------------------------------------------------------
// Fused BasicBlockA, round 5:
//  - vertical pixel-pair per thread, fma.rn.f32x2 packed fp32 math
//  - masked/compacted weights (42 live taps) duplicated into f32x2 lanes and
//    staged in __constant__ (LDCU uniform port, off the l1tex crossbar)
//  - hs double-buffered: ONE __syncthreads per latent
// ---------------------------------------------------------------------------

#define L_DIM 16
#define WSLOT 44
#define TX 32
#define TY 16
#define XS_H 19       // x tile rows: gy0-2 .. gy0+16
#define XS_W 36       // x tile cols: gx0-2 .. gx0+33
#define HS_H 18       // h rows gy0-1 .. gy0+16 (row 17 is padding, masked 0)
#define HS_W 34       // h cols gx0-1 .. gx0+32
#define NPAIR 306     // 9 pair-rows * 34 cols

typedef unsigned long long u64;

struct WB {
    u64 w[2][L_DIM][WSLOT];   // each u64 = f32x2 with both lanes = weight
    u64 b[L_DIM][3];
};
__device__ WB g_wb;
__constant__ WB c_wb;

__device__ __forceinline__ float softplus_f(float v) {
    return fmaxf(v, 0.f) + log1pf(expf(-fabsf(v)));
}

__device__ __forceinline__ u64 pack2(float lo, float hi) {
    u64 r;
    asm("mov.b64 %0, {%1, %2};" : "=l"(r) : "f"(lo), "f"(hi));
    return r;
}
__device__ __forceinline__ void unpack2(u64 v, float& lo, float& hi) {
    asm("mov.b64 {%0, %1}, %2;" : "=f"(lo), "=f"(hi) : "l"(v));
}
__device__ __forceinline__ u64 fma2(u64 a, u64 b, u64 c) {
    u64 d;
    asm("fma.rn.f32x2 %0, %1, %2, %3;" : "=l"(d) : "l"(a), "l"(b), "l"(c));
    return d;
}

// Tap offset of (out ch i, in ch j) group in the 42-tap compact layout.
__device__ __forceinline__ constexpr int woff(int i, int j) {
    constexpr int tbl[9] = {0, 5, 9, 13, 18, 23, 27, 32, 37};
    return tbl[i * 3 + j];
}

__global__ void prep_kernel(const float* __restrict__ w1, const float* __restrict__ c1,
                            const float* __restrict__ bias1,
                            const float* __restrict__ w2, const float* __restrict__ c2) {
    int t = threadIdx.x;
    if (t >= 2 * L_DIM) return;
    int stage = t >> 4;
    int l = t & 15;
    const float* W = stage ? w2 : w1;
    const float* C = stage ? c2 : c1;
    u64* dst = g_wb.w[stage][l];
    int s = 0;
    for (int i = 0; i < 3; i++) {
        for (int j = 0; j < 3; j++) {
            int base = ((l * 3 + i) * 3 + j) * 9;
            for (int kx = 0; kx < 3; kx++) { float v = W[base + kx]; dst[s++] = pack2(v, v); }
            { float v = W[base + 3]; dst[s++] = pack2(v, v); }           // ky=1,kx=0
            if (j <= i) {
                float v = (j == i) ? softplus_f(C[base + 4]) : W[base + 4];
                dst[s++] = pack2(v, v);
            }
        }
    }
    dst[42] = 0ull; dst[43] = 0ull;
    if (stage == 0) {
        for (int i = 0; i < 3; i++) { float v = bias1[l * 3 + i]; g_wb.b[l][i] = pack2(v, v); }
    }
}

// 42 packed FMAs: a[i] += sum over taps. s[j][0..2]=ky0 kx0..2, [3]=ky1kx0, [4]=ky1kx1.
__device__ __forceinline__ void conv42_2(const u64* __restrict__ w, u64 a[3],
                                         const u64 (&s)[3][5]) {
#pragma unroll
    for (int j = 0; j < 3; j++) {
#pragma unroll
        for (int i = 0; i < 3; i++) {
            const int o = woff(i, j);
            a[i] = fma2(w[o + 0], s[j][0], a[i]);
            a[i] = fma2(w[o + 1], s[j][1], a[i]);
            a[i] = fma2(w[o + 2], s[j][2], a[i]);
            a[i] = fma2(w[o + 3], s[j][3], a[i]);
            if (j <= i) a[i] = fma2(w[o + 4], s[j][4], a[i]);
        }
    }
}

__device__ __forceinline__ float elu_f(float v) {
    return (v > 0.f) ? v : (__expf(v) - 1.f);
}

__global__ __launch_bounds__(256, 2)
void fused_kernel(const float* __restrict__ x, const float* __restrict__ res,
                  float* __restrict__ out) {
    __shared__ float xs[3][XS_H][XS_W];
    __shared__ float hs[2][3][HS_H][HS_W];

    const int tid = threadIdx.x;
    const int b   = blockIdx.z;
    const int gy0 = blockIdx.y * TY;
    const int gx0 = blockIdx.x * TX;

    // ---- x tile with halo (zero outside image) ----
    const float* xb = x + (size_t)b * 3 * 128 * 128;
    for (int q = tid; q < 3 * XS_H * XS_W; q += 256) {
        int c  = q / (XS_H * XS_W);
        int r  = (q / XS_W) % XS_H;
        int cc = q % XS_W;
        int gy = gy0 - 2 + r;
        int gx = gx0 - 2 + cc;
        float v = 0.f;
        if ((unsigned)gy < 128u && (unsigned)gx < 128u)
            v = xb[(c * 128 + gy) * 128 + gx];
        xs[c][r][cc] = v;
    }
    __syncthreads();

    // ---- stage-1 pair assignments ----
    const int pr0 = tid / HS_W, pc0 = tid % HS_W;           // pair 0: h rows 2pr0, 2pr0+1
    const bool has1 = (tid >= 206);
    const int p1  = tid + 50;                                // pairs 256..305
    const int pr1 = p1 / HS_W, pc1 = p1 % HS_W;

    const int gY0 = gy0 - 1 + 2 * pr0;
    const bool cok0 = ((unsigned)(gx0 - 1 + pc0) < 128u);
    const bool v00 = cok0 && ((unsigned)gY0 < 128u);
    const bool v01 = cok0 && ((unsigned)(gY0 + 1) < 128u);
    const int gY1 = gy0 - 1 + 2 * pr1;
    const bool cok1 = ((unsigned)(gx0 - 1 + pc1) < 128u);
    const bool v10 = cok1 && ((unsigned)gY1 < 128u);
    const bool v11 = cok1 && ((unsigned)(gY1 + 1) < 128u);

    // hoist stage-1 sources for pair 0 (latent-invariant)
    u64 s1s[3][5];
#pragma unroll
    for (int j = 0; j < 3; j++) {
        s1s[j][0] = pack2(xs[j][2 * pr0][pc0],     xs[j][2 * pr0 + 1][pc0]);
        s1s[j][1] = pack2(xs[j][2 * pr0][pc0 + 1], xs[j][2 * pr0 + 1][pc0 + 1]);
        s1s[j][2] = pack2(xs[j][2 * pr0][pc0 + 2], xs[j][2 * pr0 + 1][pc0 + 2]);
        s1s[j][3] = pack2(xs[j][2 * pr0 + 1][pc0],     xs[j][2 * pr0 + 2][pc0]);
        s1s[j][4] = pack2(xs[j][2 * pr0 + 1][pc0 + 1], xs[j][2 * pr0 + 2][pc0 + 1]);
    }

    const int tx = tid & 31;
    const int py = tid >> 5;          // output pair-row 0..7

    u64 acc[3];
    acc[0] = acc[1] = acc[2] = pack2(0.f, 0.f);

    for (int l = 0; l < L_DIM; l++) {
        const int buf = l & 1;
        // ---- stage 1 ----
        {
            const u64* w = c_wb.w[0][l];
            u64 a[3] = {c_wb.b[l][0], c_wb.b[l][1], c_wb.b[l][2]};
            conv42_2(w, a, s1s);
#pragma unroll
            for (int i = 0; i < 3; i++) {
                float lo, hi;
                unpack2(a[i], lo, hi);
                hs[buf][i][2 * pr0][pc0]     = v00 ? elu_f(lo) : 0.f;
                hs[buf][i][2 * pr0 + 1][pc0] = v01 ? elu_f(hi) : 0.f;
            }
            if (has1) {
                u64 s[3][5];
#pragma unroll
                for (int j = 0; j < 3; j++) {
                    s[j][0] = pack2(xs[j][2 * pr1][pc1],     xs[j][2 * pr1 + 1][pc1]);
                    s[j][1] = pack2(xs[j][2 * pr1][pc1 + 1], xs[j][2 * pr1 + 1][pc1 + 1]);
                    s[j][2] = pack2(xs[j][2 * pr1][pc1 + 2], xs[j][2 * pr1 + 1][pc1 + 2]);
                    s[j][3] = pack2(xs[j][2 * pr1 + 1][pc1],     xs[j][2 * pr1 + 2][pc1]);
                    s[j][4] = pack2(xs[j][2 * pr1 + 1][pc1 + 1], xs[j][2 * pr1 + 2][pc1 + 1]);
                }
                u64 a1[3] = {c_wb.b[l][0], c_wb.b[l][1], c_wb.b[l][2]};
                conv42_2(w, a1, s);
#pragma unroll
                for (int i = 0; i < 3; i++) {
                    float lo, hi;
                    unpack2(a1[i], lo, hi);
                    hs[buf][i][2 * pr1][pc1]     = v10 ? elu_f(lo) : 0.f;
                    hs[buf][i][2 * pr1 + 1][pc1] = v11 ? elu_f(hi) : 0.f;
                }
            }
        }
        __syncthreads();

        // ---- stage 2 (accumulate directly into acc) ----
        {
            const u64* w = c_wb.w[1][l];
            u64 s[3][5];
#pragma unroll
            for (int j = 0; j < 3; j++) {
                s[j][0] = pack2(hs[buf][j][2 * py][tx],     hs[buf][j][2 * py + 1][tx]);
                s[j][1] = pack2(hs[buf][j][2 * py][tx + 1], hs[buf][j][2 * py + 1][tx + 1]);
                s[j][2] = pack2(hs[buf][j][2 * py][tx + 2], hs[buf][j][2 * py + 1][tx + 2]);
                s[j][3] = pack2(hs[buf][j][2 * py + 1][tx],     hs[buf][j][2 * py + 2][tx]);
                s[j][4] = pack2(hs[buf][j][2 * py + 1][tx + 1], hs[buf][j][2 * py + 2][tx + 1]);
            }
            conv42_2(w, acc, s);
        }
        // no second sync: next latent writes the other hs buffer
    }

    // ---- epilogue: mean + gated residual, two rows per thread ----
    const float r = res[0];
    const float g = (r > 0.f) ? r : 0.f;
    const int gy = gy0 + 2 * py;
    const int gx = gx0 + tx;
    float* ob = out + (size_t)b * 3 * 128 * 128;
#pragma unroll
    for (int i = 0; i < 3; i++) {
        float lo, hi;
        unpack2(acc[i], lo, hi);
        ob[(i * 128 + gy) * 128 + gx] =
            lo * (1.f / 16.f) + g * xs[i][2 * py + 2][tx + 2];
        ob[(i * 128 + gy + 1) * 128 + gx] =
            hi * (1.f / 16.f) + g * xs[i][2 * py + 3][tx + 2];
    }
}

extern "C" void kernel_launch(void* const* d_in, const int* in_sizes, int n_in,
                              void* d_out, int out_size) {
    const float* x  = (const float*)d_in[0];
    const float* w1 = (const float*)d_in[1];
    const float* c1 = (const float*)d_in[2];
    const float* b1 = (const float*)d_in[3];
    const float* w2 = (const float*)d_in[4];
    const float* c2 = (const float*)d_in[5];
    const float* rs = (const float*)d_in[6];
    (void)in_sizes; (void)n_in; (void)out_size;

    prep_kernel<<<1, 32>>>(w1, c1, b1, w2, c2);

    void* src = nullptr;
    cudaGetSymbolAddress(&src, g_wb);
    cudaMemcpyToSymbolAsync(c_wb, src, sizeof(WB), 0, cudaMemcpyDeviceToDevice, 0);

    dim3 grid(128 / TX, 128 / TY, 64);
    fused_kernel<<<grid, 256>>>(x, rs, (float*)d_out);
}

// round 7
// speedup vs baseline: 1.2233x; 1.2233x over previous
#include <cuda_runtime.h>

// ---------------------------------------------------------------------------
// Fused BasicBlockA, round 7 (= round 6 + OOB guard fix).
//  - f32x2 packed math, one vertical pixel-pair per thread (32x16 tile).
//  - x and h tiles stored in SMEM as u64 row-pair words: pack2(h[2r],h[2r+1]).
//    Even-parity taps = direct LDS.64; odd-parity taps = register recombine
//    cmb(A,B) = pack2(A.hi, B.lo)  (pure reg moves, no extra smem traffic).
//  - weights: masked/compacted 42 live taps, PLAIN floats in SMEM, j-major
//    16-float chunks -> 4 LDS.128 broadcasts per (stage, j); lane-dup in regs.
//  - hs double buffered: ONE __syncthreads per latent.
// ---------------------------------------------------------------------------

#define L_DIM 16
#define TX 32
#define TY 16
#define XQ 10        // xsE pair-rows: pair q = x rel rows (2q-4, 2q-3)
#define PS 9         // hsE pair-rows: pair p = h rel rows (2p-2, 2p-1)
#define XCOLS 36     // x col cc -> rel col cc-2
#define HCOLS 34     // h col cc -> rel col cc-1

typedef unsigned long long u64;

struct WB2 {
    float w[2][L_DIM][3][16];  // [stage][latent][j][chunk16]
    u64   b[L_DIM][3];         // bias, lane-duplicated
};
__device__ WB2 g_wb;

__device__ __forceinline__ float softplus_f(float v) {
    return fmaxf(v, 0.f) + log1pf(expf(-fabsf(v)));
}
__device__ __forceinline__ u64 pack2(float lo, float hi) {
    u64 r; asm("mov.b64 %0, {%1, %2};" : "=l"(r) : "f"(lo), "f"(hi)); return r;
}
__device__ __forceinline__ void unpack2(u64 v, float& lo, float& hi) {
    asm("mov.b64 {%0, %1}, %2;" : "=f"(lo), "=f"(hi) : "l"(v));
}
__device__ __forceinline__ u64 fma2(u64 a, u64 b, u64 c) {
    u64 d; asm("fma.rn.f32x2 %0, %1, %2, %3;" : "=l"(d) : "l"(a), "l"(b), "l"(c)); return d;
}
__device__ __forceinline__ u64 dup2(float f) { return pack2(f, f); }
// (A.hi, B.lo): odd-parity pair from two even-parity words. Register-only.
__device__ __forceinline__ u64 cmb(u64 A, u64 B) {
    float al, ah, bl, bh;
    unpack2(A, al, ah); unpack2(B, bl, bh);
    return pack2(ah, bl);
}

// chunk-internal offset of (out ch i) group within j-chunk
__device__ __host__ __forceinline__ constexpr int goff(int j, int i) {
    // group sizes: 4 + (j<=i)
    constexpr int t[3][3] = {{0, 5, 10}, {0, 4, 9}, {0, 4, 8}};
    return t[j][i];
}

__global__ void prep_kernel(const float* __restrict__ w1, const float* __restrict__ c1,
                            const float* __restrict__ bias1,
                            const float* __restrict__ w2, const float* __restrict__ c2) {
    int t = threadIdx.x;
    if (t >= 2 * L_DIM) return;
    int stage = t >> 4;
    int l = t & 15;
    const float* W = stage ? w2 : w1;
    const float* C = stage ? c2 : c1;
    for (int j = 0; j < 3; j++) {
        float* dst = g_wb.w[stage][l][j];
        for (int k = 0; k < 16; k++) dst[k] = 0.f;
        for (int i = 0; i < 3; i++) {
            int base = ((l * 3 + i) * 3 + j) * 9;
            int k = goff(j, i);
            dst[k + 0] = W[base + 0];     // ky0 kx0
            dst[k + 1] = W[base + 1];     // ky0 kx1
            dst[k + 2] = W[base + 2];     // ky0 kx2
            dst[k + 3] = W[base + 3];     // ky1 kx0
            if (j <= i)
                dst[k + 4] = (j == i) ? softplus_f(C[base + 4]) : W[base + 4];
        }
    }
    if (stage == 0)
        for (int i = 0; i < 3; i++) g_wb.b[l][i] = dup2(bias1[l * 3 + i]);
}

// one j-chunk of the 42-tap conv. s0..s2: ky0 kx0..2 (odd pairs),
// s3: ky1 kx0, s4: ky1 kx1 (even pairs). wp -> 16-float chunk in SMEM.
template <int J>
__device__ __forceinline__ void conv_j(const float* __restrict__ wp, u64 a[3],
                                       u64 s0, u64 s1, u64 s2, u64 s3, u64 s4) {
    alignas(16) float wf[16];
    ((float4*)wf)[0] = ((const float4*)wp)[0];
    ((float4*)wf)[1] = ((const float4*)wp)[1];
    ((float4*)wf)[2] = ((const float4*)wp)[2];
    ((float4*)wf)[3] = ((const float4*)wp)[3];
#pragma unroll
    for (int i = 0; i < 3; i++) {
        const int k = goff(J, i);
        a[i] = fma2(dup2(wf[k + 0]), s0, a[i]);
        a[i] = fma2(dup2(wf[k + 1]), s1, a[i]);
        a[i] = fma2(dup2(wf[k + 2]), s2, a[i]);
        a[i] = fma2(dup2(wf[k + 3]), s3, a[i]);
        if (J <= i) a[i] = fma2(dup2(wf[k + 4]), s4, a[i]);
    }
}

__device__ __forceinline__ float elu_f(float v) {
    return (v > 0.f) ? v : (__expf(v) - 1.f);
}

// full 42-tap conv from a pair-layout tile. Pair index p, col index cc.
// even pair (ky=1 rows) = tile[p+1]; odd pair (ky=0 rows) = cmb(tile[p], tile[p+1]).
__device__ __forceinline__ void conv_tile(const float* __restrict__ wl,
                                          const u64* __restrict__ tile,
                                          int pstride, int cstride_rows, int p, int cc,
                                          u64 a[3]) {
    // tile layout: tile[j*cstride_rows + pair*pstride + col]
#pragma unroll
    for (int j = 0; j < 3; j++) {
        const u64* tj = tile + j * cstride_rows + p * pstride + cc;
        u64 L0 = tj[0], L1 = tj[1], L2 = tj[2];
        const u64* tj1 = tj + pstride;
        u64 M0 = tj1[0], M1 = tj1[1], M2 = tj1[2];
        u64 s0 = cmb(L0, M0), s1 = cmb(L1, M1), s2 = cmb(L2, M2);
        if (j == 0) conv_j<0>(wl + 0 * 16, a, s0, s1, s2, M0, M1);
        if (j == 1) conv_j<1>(wl + 1 * 16, a, s0, s1, s2, M0, M1);
        if (j == 2) conv_j<2>(wl + 2 * 16, a, s0, s1, s2, M0, M1);
    }
}

__global__ __launch_bounds__(256, 2)
void fused_kernel(const float* __restrict__ x, const float* __restrict__ res,
                  float* __restrict__ out) {
    __shared__ u64 xsE[3][XQ][XCOLS];
    __shared__ u64 hsE[2][3][PS][HCOLS];
    __shared__ alignas(16) WB2 swb;

    const int tid = threadIdx.x;
    const int b   = blockIdx.z;
    const int gy0 = blockIdx.y * TY;
    const int gx0 = blockIdx.x * TX;

    // ---- weights/bias into SMEM (plain u64 copy of the struct) ----
    {
        const u64* src = (const u64*)&g_wb;
        u64* dst = (u64*)&swb;
        const int n = sizeof(WB2) / 8;
        for (int q = tid; q < n; q += 256) dst[q] = src[q];
    }

    // ---- x tile in pair layout: xsE[j][q][cc] = pack2(x rel 2q-4, 2q-3) ----
    const float* xb = x + (size_t)b * 3 * 128 * 128;
    for (int q = tid; q < 3 * XQ * XCOLS; q += 256) {
        int j  = q / (XQ * XCOLS);
        int r  = (q / XCOLS) % XQ;
        int cc = q % XCOLS;
        int gy = gy0 + 2 * r - 4;
        int gx = gx0 + cc - 2;
        float lo = 0.f, hi = 0.f;
        if ((unsigned)gx < 128u) {
            const float* col = xb + (size_t)j * 128 * 128 + gx;
            if ((unsigned)gy < 128u)       lo = col[(size_t)gy * 128];
            if ((unsigned)(gy + 1) < 128u) hi = col[(size_t)(gy + 1) * 128];
        }
        xsE[j][r][cc] = pack2(lo, hi);
    }
    __syncthreads();

    // ---- stage-1 task assignment (latent-invariant) ----
    // task t: pair ps = t/HCOLS (h rel rows 2ps-2, 2ps-1), col cc (rel cc-1)
    const int ps0 = tid / HCOLS, cc0 = tid % HCOLS;
    const bool cok0 = ((unsigned)(gx0 + cc0 - 1) < 128u);
    const bool v0lo = cok0 && ((unsigned)(gy0 + 2 * ps0 - 2) < 128u);
    const bool v0hi = cok0 && ((unsigned)(gy0 + 2 * ps0 - 1) < 128u);
    const int t1  = tid + 256;
    const bool has1 = (t1 < PS * HCOLS);              // 306 tasks total -> tid < 50
    const int ps1 = t1 / HCOLS, cc1 = t1 % HCOLS;
    const bool cok1 = ((unsigned)(gx0 + cc1 - 1) < 128u);
    const bool v1lo = has1 && cok1 && ((unsigned)(gy0 + 2 * ps1 - 2) < 128u);
    const bool v1hi = has1 && cok1 && ((unsigned)(gy0 + 2 * ps1 - 1) < 128u);

    const int tx = tid & 31;
    const int py = tid >> 5;            // output pair row 0..7

    u64 acc[3];
    acc[0] = acc[1] = acc[2] = pack2(0.f, 0.f);

    for (int l = 0; l < L_DIM; l++) {
        const int buf = l & 1;
        const float* w1l = &swb.w[0][l][0][0];

        // ---- stage 1, task 0 ----
        {
            u64 a[3] = {swb.b[l][0], swb.b[l][1], swb.b[l][2]};
            conv_tile(w1l, &xsE[0][0][0], XCOLS, XQ * XCOLS, ps0, cc0, a);
#pragma unroll
            for (int i = 0; i < 3; i++) {
                float lo, hi; unpack2(a[i], lo, hi);
                lo = v0lo ? elu_f(lo) : 0.f;
                hi = v0hi ? elu_f(hi) : 0.f;
                hsE[buf][i][ps0][cc0] = pack2(lo, hi);
            }
        }
        // ---- stage 1, task 1 (50 threads) ----
        if (has1) {
            u64 a[3] = {swb.b[l][0], swb.b[l][1], swb.b[l][2]};
            conv_tile(w1l, &xsE[0][0][0], XCOLS, XQ * XCOLS, ps1, cc1, a);
#pragma unroll
            for (int i = 0; i < 3; i++) {
                float lo, hi; unpack2(a[i], lo, hi);
                lo = v1lo ? elu_f(lo) : 0.f;
                hi = v1hi ? elu_f(hi) : 0.f;
                hsE[buf][i][ps1][cc1] = pack2(lo, hi);
            }
        }
        __syncthreads();

        // ---- stage 2: accumulate into acc ----
        conv_tile(&swb.w[1][l][0][0], &hsE[buf][0][0][0], HCOLS, PS * HCOLS, py, tx, acc);
        // no second sync: next latent writes the other hs buffer
    }

    // ---- epilogue: mean over latents + gated residual ----
    const float r = res[0];
    const float g = (r > 0.f) ? r : 0.f;
    const int gy = gy0 + 2 * py;
    const int gx = gx0 + tx;
    float* ob = out + (size_t)b * 3 * 128 * 128;
#pragma unroll
    for (int i = 0; i < 3; i++) {
        float lo, hi; unpack2(acc[i], lo, hi);
        float xlo, xhi; unpack2(xsE[i][py + 2][tx + 2], xlo, xhi);  // x rel rows 2py,2py+1
        ob[(i * 128 + gy) * 128 + gx]       = lo * (1.f / 16.f) + g * xlo;
        ob[(i * 128 + gy + 1) * 128 + gx]   = hi * (1.f / 16.f) + g * xhi;
    }
}

extern "C" void kernel_launch(void* const* d_in, const int* in_sizes, int n_in,
                              void* d_out, int out_size) {
    const float* x  = (const float*)d_in[0];
    const float* w1 = (const float*)d_in[1];
    const float* c1 = (const float*)d_in[2];
    const float* b1 = (const float*)d_in[3];
    const float* w2 = (const float*)d_in[4];
    const float* c2 = (const float*)d_in[5];
    const float* rs = (const float*)d_in[6];
    (void)in_sizes; (void)n_in; (void)out_size;

    prep_kernel<<<1, 32>>>(w1, c1, b1, w2, c2);

    dim3 grid(128 / TX, 128 / TY, 64);
    fused_kernel<<<grid, 256>>>(x, rs, (float*)d_out);
}

// round 8
// speedup vs baseline: 1.4650x; 1.1977x over previous
#include <cuda_runtime.h>

// ---------------------------------------------------------------------------
// Fused BasicBlockA, round 8.
//  - 2x2 output pixels per thread: 2 adjacent columns x 1 vertical f32x2 pair.
//  - x/h tiles in SMEM as u64 row-pair words; odd taps via register cmb().
//  - ODD u64 row strides (37/35) to kill stride-2 bank conflicts.
//  - 128-thread blocks (32x16 tile), no min-blocks bound -> ~5 blocks/SM.
//  - weights: 42 live masked taps as plain floats, j-major 16-float chunks.
//  - hs double buffered: one __syncthreads per latent.
// ---------------------------------------------------------------------------

#define L_DIM 16
#define TX 32
#define TY 16
#define NT 128
#define XQ 10        // x pair q = x rel rows (2q-4, 2q-3)
#define PS 9         // h pair p = h rel rows (2p-2, 2p-1)
#define XCOLS 37     // x storage col = rel col + 2 (rel -2..33), padded odd
#define HCOLS 35     // h storage col = rel col + 1 (rel -1..32), padded odd
#define NS1 (PS * 17)  // 153 stage-1 tasks (17 col-pairs x 9 pair-rows)

typedef unsigned long long u64;

struct WB2 {
    float w[2][L_DIM][3][16];  // [stage][latent][j][chunk16]
    u64   b[L_DIM][3];
};
__device__ WB2 g_wb;

__device__ __forceinline__ float softplus_f(float v) {
    return fmaxf(v, 0.f) + log1pf(expf(-fabsf(v)));
}
__device__ __forceinline__ u64 pack2(float lo, float hi) {
    u64 r; asm("mov.b64 %0, {%1, %2};" : "=l"(r) : "f"(lo), "f"(hi)); return r;
}
__device__ __forceinline__ void unpack2(u64 v, float& lo, float& hi) {
    asm("mov.b64 {%0, %1}, %2;" : "=f"(lo), "=f"(hi) : "l"(v));
}
__device__ __forceinline__ u64 fma2(u64 a, u64 b, u64 c) {
    u64 d; asm("fma.rn.f32x2 %0, %1, %2, %3;" : "=l"(d) : "l"(a), "l"(b), "l"(c)); return d;
}
__device__ __forceinline__ u64 dup2(float f) { return pack2(f, f); }
// (A.hi, B.lo): odd-parity pair from two even-parity row-pair words.
__device__ __forceinline__ u64 cmb(u64 A, u64 B) {
    float al, ah, bl, bh;
    unpack2(A, al, ah); unpack2(B, bl, bh);
    return pack2(ah, bl);
}

__device__ __host__ __forceinline__ constexpr int goff(int j, int i) {
    constexpr int t[3][3] = {{0, 5, 10}, {0, 4, 9}, {0, 4, 8}};
    return t[j][i];
}

__global__ void prep_kernel(const float* __restrict__ w1, const float* __restrict__ c1,
                            const float* __restrict__ bias1,
                            const float* __restrict__ w2, const float* __restrict__ c2) {
    int t = threadIdx.x;
    if (t >= 2 * L_DIM) return;
    int stage = t >> 4;
    int l = t & 15;
    const float* W = stage ? w2 : w1;
    const float* C = stage ? c2 : c1;
    for (int j = 0; j < 3; j++) {
        float* dst = g_wb.w[stage][l][j];
        for (int k = 0; k < 16; k++) dst[k] = 0.f;
        for (int i = 0; i < 3; i++) {
            int base = ((l * 3 + i) * 3 + j) * 9;
            int k = goff(j, i);
            dst[k + 0] = W[base + 0];
            dst[k + 1] = W[base + 1];
            dst[k + 2] = W[base + 2];
            dst[k + 3] = W[base + 3];
            if (j <= i)
                dst[k + 4] = (j == i) ? softplus_f(C[base + 4]) : W[base + 4];
        }
    }
    if (stage == 0)
        for (int i = 0; i < 3; i++) g_wb.b[l][i] = dup2(bias1[l * 3 + i]);
}

// One j-chunk, one column: s0..s2 = ky0 kx0..2 (odd pairs), s3,s4 = ky1 kx0,1.
template <int J>
__device__ __forceinline__ void conv_j(const float (&wf)[16], u64 a[3],
                                       u64 s0, u64 s1, u64 s2, u64 s3, u64 s4) {
#pragma unroll
    for (int i = 0; i < 3; i++) {
        const int k = goff(J, i);
        a[i] = fma2(dup2(wf[k + 0]), s0, a[i]);
        a[i] = fma2(dup2(wf[k + 1]), s1, a[i]);
        a[i] = fma2(dup2(wf[k + 2]), s2, a[i]);
        a[i] = fma2(dup2(wf[k + 3]), s3, a[i]);
        if (J <= i) a[i] = fma2(dup2(wf[k + 4]), s4, a[i]);
    }
}

__device__ __forceinline__ float elu_f(float v) {
    return (v > 0.f) ? v : (__expf(v) - 1.f);
}

// Two adjacent columns (cc, cc+1 sources span cc..cc+3), one pair row p.
// tile[j*chstride + pair*pstride + col]; aA/aB are col A/B accumulators.
__device__ __forceinline__ void conv2(const float* __restrict__ wl,
                                      const u64* __restrict__ tile,
                                      int pstride, int chstride, int p, int cc,
                                      u64 aA[3], u64 aB[3]) {
#pragma unroll
    for (int j = 0; j < 3; j++) {
        const u64* tj = tile + j * chstride + p * pstride + cc;
        u64 L0 = tj[0], L1 = tj[1], L2 = tj[2], L3 = tj[3];
        const u64* tm = tj + pstride;
        u64 M0 = tm[0], M1 = tm[1], M2 = tm[2], M3 = tm[3];
        u64 o0 = cmb(L0, M0), o1 = cmb(L1, M1), o2 = cmb(L2, M2), o3 = cmb(L3, M3);
        alignas(16) float wf[16];
        ((float4*)wf)[0] = ((const float4*)(wl + j * 16))[0];
        ((float4*)wf)[1] = ((const float4*)(wl + j * 16))[1];
        ((float4*)wf)[2] = ((const float4*)(wl + j * 16))[2];
        ((float4*)wf)[3] = ((const float4*)(wl + j * 16))[3];
        if (j == 0) { conv_j<0>(wf, aA, o0, o1, o2, M0, M1); conv_j<0>(wf, aB, o1, o2, o3, M1, M2); }
        if (j == 1) { conv_j<1>(wf, aA, o0, o1, o2, M0, M1); conv_j<1>(wf, aB, o1, o2, o3, M1, M2); }
        if (j == 2) { conv_j<2>(wf, aA, o0, o1, o2, M0, M1); conv_j<2>(wf, aB, o1, o2, o3, M1, M2); }
    }
}

__global__ __launch_bounds__(NT)
void fused_kernel(const float* __restrict__ x, const float* __restrict__ res,
                  float* __restrict__ out) {
    __shared__ alignas(16) WB2 swb;
    __shared__ u64 xsE[3][XQ][XCOLS];
    __shared__ u64 hsE[2][3][PS][HCOLS];

    const int tid = threadIdx.x;
    const int b   = blockIdx.z;
    const int gy0 = blockIdx.y * TY;
    const int gx0 = blockIdx.x * TX;

    // ---- weights/bias into SMEM ----
    {
        const u64* src = (const u64*)&g_wb;
        u64* dst = (u64*)&swb;
        const int n = sizeof(WB2) / 8;
        for (int q = tid; q < n; q += NT) dst[q] = src[q];
    }

    // ---- x tile, pair layout: xsE[j][q][xcc] = pack2(rel row 2q-4, 2q-3), rel col xcc-2
    const float* xb = x + (size_t)b * 3 * 128 * 128;
    for (int q = tid; q < 3 * XQ * XCOLS; q += NT) {
        int j  = q / (XQ * XCOLS);
        int r  = (q / XCOLS) % XQ;
        int cc = q % XCOLS;
        int gy = gy0 + 2 * r - 4;
        int gx = gx0 + cc - 2;
        float lo = 0.f, hi = 0.f;
        if ((unsigned)gx < 128u) {
            const float* col = xb + (size_t)j * 128 * 128 + gx;
            if ((unsigned)gy < 128u)       lo = col[(size_t)gy * 128];
            if ((unsigned)(gy + 1) < 128u) hi = col[(size_t)(gy + 1) * 128];
        }
        xsE[j][r][cc] = pack2(lo, hi);
    }
    __syncthreads();

    // ---- stage-1 task decode (latent-invariant) ----
    // task u: pcol = u%17 -> h storage cols 2pcol, 2pcol+1 ; pair ps = u/17
    const int pc0 = tid % 17, ps0 = tid / 17;
    const int hcA0 = 2 * pc0, hcB0 = hcA0 + 1;
    const bool cokA0 = ((unsigned)(gx0 + hcA0 - 1) < 128u);
    const bool cokB0 = ((unsigned)(gx0 + hcB0 - 1) < 128u);
    const bool rlo0  = ((unsigned)(gy0 + 2 * ps0 - 2) < 128u);
    const bool rhi0  = ((unsigned)(gy0 + 2 * ps0 - 1) < 128u);

    const int t1 = tid + NT;
    const bool has1 = (t1 < NS1);              // 153 tasks -> tid < 25
    const int pc1 = t1 % 17, ps1 = t1 / 17;
    const int hcA1 = 2 * pc1, hcB1 = hcA1 + 1;
    const bool cokA1 = ((unsigned)(gx0 + hcA1 - 1) < 128u);
    const bool cokB1 = ((unsigned)(gx0 + hcB1 - 1) < 128u);
    const bool rlo1  = ((unsigned)(gy0 + 2 * ps1 - 2) < 128u);
    const bool rhi1  = ((unsigned)(gy0 + 2 * ps1 - 1) < 128u);

    const int tcx = tid % 16;           // out col pair: cols 2tcx, 2tcx+1
    const int tpy = tid / 16;           // out pair row: rows 2tpy, 2tpy+1

    u64 accA[3], accB[3];
    accA[0] = accA[1] = accA[2] = pack2(0.f, 0.f);
    accB[0] = accB[1] = accB[2] = pack2(0.f, 0.f);

    for (int l = 0; l < L_DIM; l++) {
        const int buf = l & 1;
        const float* w1l = &swb.w[0][l][0][0];
        const u64 bl0 = swb.b[l][0], bl1 = swb.b[l][1], bl2 = swb.b[l][2];

        // ---- stage 1, task 0 ----
        {
            u64 aA[3] = {bl0, bl1, bl2}, aB[3] = {bl0, bl1, bl2};
            conv2(w1l, &xsE[0][0][0], XCOLS, XQ * XCOLS, ps0, hcA0, aA, aB);
#pragma unroll
            for (int i = 0; i < 3; i++) {
                float lo, hi;
                unpack2(aA[i], lo, hi);
                lo = (cokA0 && rlo0) ? elu_f(lo) : 0.f;
                hi = (cokA0 && rhi0) ? elu_f(hi) : 0.f;
                hsE[buf][i][ps0][hcA0] = pack2(lo, hi);
                unpack2(aB[i], lo, hi);
                lo = (cokB0 && rlo0) ? elu_f(lo) : 0.f;
                hi = (cokB0 && rhi0) ? elu_f(hi) : 0.f;
                hsE[buf][i][ps0][hcB0] = pack2(lo, hi);
            }
        }
        // ---- stage 1, task 1 (25 threads) ----
        if (has1) {
            u64 aA[3] = {bl0, bl1, bl2}, aB[3] = {bl0, bl1, bl2};
            conv2(w1l, &xsE[0][0][0], XCOLS, XQ * XCOLS, ps1, hcA1, aA, aB);
#pragma unroll
            for (int i = 0; i < 3; i++) {
                float lo, hi;
                unpack2(aA[i], lo, hi);
                lo = (cokA1 && rlo1) ? elu_f(lo) : 0.f;
                hi = (cokA1 && rhi1) ? elu_f(hi) : 0.f;
                hsE[buf][i][ps1][hcA1] = pack2(lo, hi);
                unpack2(aB[i], lo, hi);
                lo = (cokB1 && rlo1) ? elu_f(lo) : 0.f;
                hi = (cokB1 && rhi1) ? elu_f(hi) : 0.f;
                hsE[buf][i][ps1][hcB1] = pack2(lo, hi);
            }
        }
        __syncthreads();

        // ---- stage 2: out cols 2tcx,2tcx+1 -> h storage base col 2tcx ----
        conv2(&swb.w[1][l][0][0], &hsE[buf][0][0][0], HCOLS, PS * HCOLS,
              tpy, 2 * tcx, accA, accB);
        // next latent writes the other hs buffer: no second barrier
    }

    // ---- epilogue: mean over latents + gated residual ----
    const float r = res[0];
    const float g = (r > 0.f) ? r : 0.f;
    const int gy = gy0 + 2 * tpy;
    const int gxA = gx0 + 2 * tcx;
    float* ob = out + (size_t)b * 3 * 128 * 128;
#pragma unroll
    for (int i = 0; i < 3; i++) {
        float lo, hi, xlo, xhi;
        unpack2(accA[i], lo, hi);
        unpack2(xsE[i][tpy + 2][2 * tcx + 2], xlo, xhi);
        ob[(i * 128 + gy) * 128 + gxA]     = lo * (1.f / 16.f) + g * xlo;
        ob[(i * 128 + gy + 1) * 128 + gxA] = hi * (1.f / 16.f) + g * xhi;
        unpack2(accB[i], lo, hi);
        unpack2(xsE[i][tpy + 2][2 * tcx + 3], xlo, xhi);
        ob[(i * 128 + gy) * 128 + gxA + 1]     = lo * (1.f / 16.f) + g * xlo;
        ob[(i * 128 + gy + 1) * 128 + gxA + 1] = hi * (1.f / 16.f) + g * xhi;
    }
}

extern "C" void kernel_launch(void* const* d_in, const int* in_sizes, int n_in,
                              void* d_out, int out_size) {
    const float* x  = (const float*)d_in[0];
    const float* w1 = (const float*)d_in[1];
    const float* c1 = (const float*)d_in[2];
    const float* b1 = (const float*)d_in[3];
    const float* w2 = (const float*)d_in[4];
    const float* c2 = (const float*)d_in[5];
    const float* rs = (const float*)d_in[6];
    (void)in_sizes; (void)n_in; (void)out_size;

    prep_kernel<<<1, 32>>>(w1, c1, b1, w2, c2);

    dim3 grid(128 / TX, 128 / TY, 64);
    fused_kernel<<<grid, NT>>>(x, rs, (float*)d_out);
}